// round 2
// baseline (speedup 1.0000x reference)
#include <cuda_runtime.h>
#include <cuda_bf16.h>

// LearnablePeakExtractor: smooth = x * sig(10*(x-thresh)) * sig(10*(x-pooled5))
//                         mask   = smooth >= thresh
// Fused: sig(a)*sig(b) = 1/((1+e^-a)(1+e^-b)) -> 2 EX2 + 1 RCP per element.
// R2: 8 floats/thread (2x float4), streaming stores, deeper MLP.

#define ROWS 256
#define LEN  131072
#define VPR  (LEN / 4)    // float4 per row   = 32768
#define VPR2 (LEN / 8)    // vec4-pairs / row = 16384

__device__ __forceinline__ float fused2(float x, float thresh, float pooled) {
    float e1 = __expf(10.0f * (thresh - x));
    float e2 = __expf(10.0f * (pooled - x));
    return __fdividef(x, (1.0f + e1) * (1.0f + e2));
}

__global__ __launch_bounds__(256)
void peak_kernel(const float* __restrict__ in,
                 const float* __restrict__ logit_thresh,
                 float* __restrict__ out_smooth,
                 float* __restrict__ out_mask,
                 int write_mask)
{
    const int row = blockIdx.y;
    const int t   = blockIdx.x * blockDim.x + threadIdx.x;   // pair index in row

    const float4* rp = reinterpret_cast<const float4*>(in + (size_t)row * LEN);
    const int v = 2 * t;

    // front-batched loads: 4 independent LDG.128
    float4 c0 = rp[v];
    float4 c1 = rp[v + 1];
    float lx, ly, rx, ry;
    if (t > 0)         { float4 p = rp[v - 1]; lx = p.z; ly = p.w; }
    else               { lx = c0.x; ly = c0.x; }
    if (t < VPR2 - 1)  { float4 n = rp[v + 2]; rx = n.x; ry = n.y; }
    else               { rx = c1.w; ry = c1.w; }

    const float e0 = c0.x, e1 = c0.y, e2 = c0.z, e3 = c0.w;
    const float e4 = c1.x, e5 = c1.y, e6 = c1.z, e7 = c1.w;

    // 5-wide sliding max (edge-replicate == clamp window to valid range)
    float M01 = fmaxf(e0, e1);
    float M23 = fmaxf(e2, e3);
    float M45 = fmaxf(e4, e5);
    float M67 = fmaxf(e6, e7);
    float Mll = fmaxf(lx, ly);
    float Mrr = fmaxf(rx, ry);

    float p0 = fmaxf(Mll, fmaxf(M01, e2));
    float p1 = fmaxf(ly,  fmaxf(M01, M23));
    float p2 = fmaxf(M01, fmaxf(M23, e4));
    float p3 = fmaxf(e1,  fmaxf(M23, M45));
    float p4 = fmaxf(e2,  fmaxf(M23, fmaxf(M45, e6)));
    float p5 = fmaxf(e3,  fmaxf(M45, M67));
    float p6 = fmaxf(M45, fmaxf(M67, rx));
    float p7 = fmaxf(e5,  fmaxf(M67, Mrr));

    float tl = logit_thresh[0];
    float thresh = __fdividef(1.0f, 1.0f + __expf(-tl));

    float s0 = fused2(e0, thresh, p0);
    float s1 = fused2(e1, thresh, p1);
    float s2 = fused2(e2, thresh, p2);
    float s3 = fused2(e3, thresh, p3);
    float s4 = fused2(e4, thresh, p4);
    float s5 = fused2(e5, thresh, p5);
    float s6 = fused2(e6, thresh, p6);
    float s7 = fused2(e7, thresh, p7);

    const size_t voff = (size_t)row * VPR + v;
    float4* os = reinterpret_cast<float4*>(out_smooth);
    __stcs(os + voff,     make_float4(s0, s1, s2, s3));
    __stcs(os + voff + 1, make_float4(s4, s5, s6, s7));

    if (write_mask) {
        float4* om = reinterpret_cast<float4*>(out_mask);
        __stcs(om + voff,     make_float4(s0 >= thresh ? 1.0f : 0.0f,
                                          s1 >= thresh ? 1.0f : 0.0f,
                                          s2 >= thresh ? 1.0f : 0.0f,
                                          s3 >= thresh ? 1.0f : 0.0f));
        __stcs(om + voff + 1, make_float4(s4 >= thresh ? 1.0f : 0.0f,
                                          s5 >= thresh ? 1.0f : 0.0f,
                                          s6 >= thresh ? 1.0f : 0.0f,
                                          s7 >= thresh ? 1.0f : 0.0f));
    }
}

extern "C" void kernel_launch(void* const* d_in, const int* in_sizes, int n_in,
                              void* d_out, int out_size)
{
    const float* peak_map     = (const float*)d_in[0];
    const float* logit_thresh = (const float*)d_in[1];
    float* out = (float*)d_out;

    const long long N = (long long)ROWS * LEN;   // 33,554,432
    int write_mask = (out_size >= 2 * N) ? 1 : 0;

    dim3 grid(VPR2 / 256, ROWS);   // (64, 256)
    peak_kernel<<<grid, 256>>>(peak_map, logit_thresh,
                               out, out + N, write_mask);
}

// round 3
// speedup vs baseline: 1.0575x; 1.0575x over previous
#include <cuda_runtime.h>
#include <cuda_bf16.h>

// LearnablePeakExtractor: smooth = x * sig(10*(x-thresh)) * sig(10*(x-pooled5))
//                         mask   = smooth >= thresh
// Fused: sig(a)*sig(b) = 1/((1+e^-a)(1+e^-b)) -> 2 EX2 + 1 RCP per element.
// R3: R1 shape (4 floats/thread) + warp-shuffle neighbor exchange
//     (1 LDG.128/thread + 2 small edge loads per warp), normal stores.

#define ROWS 256
#define LEN  131072
#define VPR  (LEN / 4)   // float4 vectors per row = 32768

__device__ __forceinline__ float fused2(float x, float thresh, float pooled) {
    float e1 = __expf(10.0f * (thresh - x));
    float e2 = __expf(10.0f * (pooled - x));
    return __fdividef(x, (1.0f + e1) * (1.0f + e2));
}

__global__ __launch_bounds__(256)
void peak_kernel(const float* __restrict__ in,
                 const float* __restrict__ logit_thresh,
                 float* __restrict__ out_smooth,
                 float* __restrict__ out_mask,
                 int write_mask)
{
    const int row  = blockIdx.y;
    const int vc   = blockIdx.x * blockDim.x + threadIdx.x;  // vec4 index in row
    const unsigned lane = threadIdx.x & 31;

    const float* rowp = in + (size_t)row * LEN;
    const float4* rp  = reinterpret_cast<const float4*>(rowp);

    float4 c = rp[vc];

    // neighbor halo via warp shuffle; only warp-edge lanes touch memory
    float lx = __shfl_up_sync(0xFFFFFFFFu,   c.z, 1);
    float ly = __shfl_up_sync(0xFFFFFFFFu,   c.w, 1);
    float rx = __shfl_down_sync(0xFFFFFFFFu, c.x, 1);
    float ry = __shfl_down_sync(0xFFFFFFFFu, c.y, 1);

    if (lane == 0) {
        if (vc > 0) {
            float2 p = *reinterpret_cast<const float2*>(rowp + 4 * vc - 2);
            lx = p.x; ly = p.y;
        } else {
            lx = c.x; ly = c.x;      // edge replicate
        }
    }
    if (lane == 31) {
        if (vc < VPR - 1) {
            float2 n = *reinterpret_cast<const float2*>(rowp + 4 * vc + 4);
            rx = n.x; ry = n.y;
        } else {
            rx = c.w; ry = c.w;      // edge replicate
        }
    }

    // 5-wide sliding max
    float m01   = fmaxf(c.x, c.y);
    float m12   = fmaxf(c.y, c.z);
    float m23   = fmaxf(c.z, c.w);
    float m012  = fmaxf(m01, c.z);
    float m123  = fmaxf(m12, c.w);
    float m0123 = fmaxf(m01, m23);

    float p0 = fmaxf(fmaxf(lx, ly), m012);
    float p1 = fmaxf(ly, m0123);
    float p2 = fmaxf(m0123, rx);
    float p3 = fmaxf(m123, fmaxf(rx, ry));

    float tl = logit_thresh[0];
    float thresh = __fdividef(1.0f, 1.0f + __expf(-tl));

    float s0 = fused2(c.x, thresh, p0);
    float s1 = fused2(c.y, thresh, p1);
    float s2 = fused2(c.z, thresh, p2);
    float s3 = fused2(c.w, thresh, p3);

    const size_t voff = (size_t)row * VPR + vc;
    reinterpret_cast<float4*>(out_smooth)[voff] = make_float4(s0, s1, s2, s3);

    if (write_mask) {
        reinterpret_cast<float4*>(out_mask)[voff] =
            make_float4(s0 >= thresh ? 1.0f : 0.0f,
                        s1 >= thresh ? 1.0f : 0.0f,
                        s2 >= thresh ? 1.0f : 0.0f,
                        s3 >= thresh ? 1.0f : 0.0f);
    }
}

extern "C" void kernel_launch(void* const* d_in, const int* in_sizes, int n_in,
                              void* d_out, int out_size)
{
    const float* peak_map     = (const float*)d_in[0];
    const float* logit_thresh = (const float*)d_in[1];
    float* out = (float*)d_out;

    const long long N = (long long)ROWS * LEN;   // 33,554,432
    int write_mask = (out_size >= 2 * N) ? 1 : 0;

    dim3 grid(VPR / 256, ROWS);   // (128, 256)
    peak_kernel<<<grid, 256>>>(peak_map, logit_thresh,
                               out, out + N, write_mask);
}